// round 5
// baseline (speedup 1.0000x reference)
#include <cuda_runtime.h>
#include <cstdint>

#define TOPK      2000
#define NMS_THR   0.5f
#define MAXN      200000
#define MAXG      128
#define HBINS     65536
#define CAP       8192
#define CBLK      32          // ceil(TOPK/64)
#define BM        256         // proposals per block in main kernel

typedef unsigned long long ull;

// ---------------- scratch (no allocation allowed) ----------------
__device__ float               g_score[MAXN];
__device__ float4              g_boxper[MAXN];
__device__ __align__(16) int   g_hist[HBINS];    // zero at load; re-zeroed in compact
__device__ __align__(16) int   g_hcoarse[256];   // zero at load; re-zeroed in compact
__device__ int                 g_candcount;      // zero at load; reset in sort
__device__ int                 g_binB;
__device__ ull                 g_cand[CAP];
__device__ float4              g_topboxes[TOPK];
__device__ ull                 g_mask[TOPK * CBLK];

// =================== K1: fused per-proposal ==========
__global__ void __launch_bounds__(BM) main_kernel(
        const float4* __restrict__ prop,
        const float4* __restrict__ btp,   // (N*C) float4
        const float*  __restrict__ cls,
        const float4* __restrict__ gt,
        const int* __restrict__ ihp,
        const int* __restrict__ iwp,
        float4* __restrict__ out,         // full output, rows (TOPK+n)
        int N, int C, int G)
{
    __shared__ float4 sgtb[MAXG];
    __shared__ float  sga[MAXG];
    extern __shared__ float scls[];       // BM*21 floats (stride 21 -> conflict-free)

    int tid = threadIdx.x;
    int n0  = blockIdx.x * BM;

    int vi = ihp[0];
    float H = (vi > 0 && vi < 1000000) ? (float)vi : __int_as_float(vi);
    vi = iwp[0];
    float W = (vi > 0 && vi < 1000000) ? (float)vi : __int_as_float(vi);

    for (int i = tid; i < G && i < MAXG; i += BM) {
        float4 g = gt[i];
        sgtb[i] = g;
        sga[i]  = (g.z - g.x) * (g.w - g.y);
    }
    // stage cls rows (coalesced global reads)
    {
        int rows = min(BM, N - n0);
        if (rows > 0) {
            const float* cbase = cls + (size_t)n0 * C;
            if (C == 21) {
                int total = rows * 21;
                for (int idx = tid; idx < total; idx += BM) {
                    int r = idx / 21;
                    scls[r * 21 + (idx - r * 21)] = cbase[idx];
                }
            } else {
                int total = rows * C;
                for (int idx = tid; idx < total; idx += BM) {
                    int r = idx / C;
                    scls[r * 21 + (idx - r * C)] = cbase[idx];
                }
            }
        }
    }
    __syncthreads();

    int n = n0 + tid;
    if (n >= N) return;

    float4 p = prop[n];
    float pw = p.z - p.x, ph = p.w - p.y;
    float pcx = p.x + 0.5f * pw, pcy = p.y + 0.5f * ph;
    float parea = pw * ph;

    // softmax score + fg argmax (from shared)
    const float* cr = scls + tid * 21;
    float m = cr[0], bl = -1e30f; int bc = 1;
    #pragma unroll
    for (int c = 1; c < 21; c++) {
        float v = cr[c];
        m = fmaxf(m, v);
        if (v > bl) { bl = v; bc = c; }
    }
    float Z = 0.f;
    #pragma unroll
    for (int c = 0; c < 21; c++) Z += __expf(cr[c] - m);
    float score = __fdividef(__expf(bl - m), Z);

    // decode selected class box, clamp
    float4 t = btp[(size_t)n * C + bc];
    float dcx = t.x * pw + pcx;
    float dcy = t.y * ph + pcy;
    float dw  = __expf(t.z) * pw;
    float dh  = __expf(t.w) * ph;
    float4 box;
    box.x = fminf(fmaxf(dcx - 0.5f * dw, 0.f), W);
    box.y = fminf(fmaxf(dcy - 0.5f * dh, 0.f), H);
    box.z = fminf(fmaxf(dcx + 0.5f * dw, 0.f), W);
    box.w = fminf(fmaxf(dcy + 0.5f * dh, 0.f), H);

    g_boxper[n] = box;
    g_score[n]  = score;
    unsigned sbits = __float_as_uint(score);
    atomicAdd(&g_hist[sbits >> 16], 1);
    atomicAdd(&g_hcoarse[sbits >> 24], 1);

    // best-IoU gt match: argmax via cross-multiply (no division)
    float bnum = -1.0f, bden = 1.0f; int bg = 0;
    #pragma unroll 8
    for (int g = 0; g < G; g++) {
        float4 gb = sgtb[g];
        float lx = fmaxf(gb.x, p.x);
        float ly = fmaxf(gb.y, p.y);
        float rx = fminf(gb.z, p.z);
        float ry = fminf(gb.w, p.w);
        float iw = fmaxf(rx - lx, 0.f), ihh = fmaxf(ry - ly, 0.f);
        float inter = iw * ihh;
        float den = sga[g] + parea - inter;
        if (inter * bden > bnum * den) { bnum = inter; bden = den; bg = g; }
    }
    float4 gb = sgtb[bg];
    float gw = gb.z - gb.x, gh = gb.w - gb.y;
    float gcx = gb.x + 0.5f * gw, gcy = gb.y + 0.5f * gh;
    float4 rt;
    rt.x = __fdividef(gcx - pcx, pw);
    rt.y = __fdividef(gcy - pcy, ph);
    rt.z = __logf(__fdividef(gw, pw));
    rt.w = __logf(__fdividef(gh, ph));
    out[TOPK + n] = rt;
}

// helper: inclusive scan of one int over 256 threads (8 warps)
__device__ __forceinline__ int block_scan256(int v, int tid, int* wsum) {
    int lane = tid & 31, w = tid >> 5;
    int x = v;
    #pragma unroll
    for (int o = 1; o < 32; o <<= 1) {
        int y = __shfl_up_sync(0xFFFFFFFFu, x, o);
        if (lane >= o) x += y;
    }
    if (lane == 31) wsum[w] = x;
    __syncthreads();
    if (w == 0) {
        int s = (lane < 8) ? wsum[lane] : 0;
        #pragma unroll
        for (int o = 1; o < 8; o <<= 1) {
            int y = __shfl_up_sync(0xFFFFFFFFu, s, o);
            if (lane >= o) s += y;
        }
        if (lane < 8) wsum[lane] = s;
    }
    __syncthreads();
    return x + ((w > 0) ? wsum[w - 1] : 0);
}

// =================== K2: findbin via coarse + fine scan (1 block, ~2us) ====
__global__ void __launch_bounds__(256) findbin_kernel() {
    __shared__ int wsum[8];
    __shared__ int s_cb, s_excl;
    int tid = threadIdx.x;

    // pass 1: coarse bins, descending (thread t owns coarse bin 255-t)
    int v = g_hcoarse[255 - tid];
    int incl = block_scan256(v, tid, wsum);
    int excl = incl - v;
    if (excl < TOPK && incl >= TOPK) { s_cb = 255 - tid; s_excl = excl; }
    __syncthreads();

    // pass 2: fine bins inside coarse bin s_cb, descending
    int cb = s_cb, base_excl = s_excl;
    int fbin = (cb << 8) + 255 - tid;
    int v2 = g_hist[fbin];
    __syncthreads();                 // wsum reuse
    int incl2 = base_excl + block_scan256(v2, tid, wsum);
    int excl2 = incl2 - v2;
    if (excl2 < TOPK && incl2 >= TOPK) g_binB = fbin;
}

// =================== K3: compact + hist re-zero ============
__global__ void __launch_bounds__(256) compact_kernel(int N) {
    int gid = blockIdx.x * 256 + threadIdx.x;
    if (gid < N) {
        unsigned bits = __float_as_uint(g_score[gid]);
        if ((int)(bits >> 16) >= g_binB) {
            int pos = atomicAdd(&g_candcount, 1);
            if (pos < CAP)
                g_cand[pos] = ((ull)bits << 32) | (unsigned)(~gid);
        }
    }
    if (gid < HBINS) g_hist[gid] = 0;      // parallel re-zero for next replay
    if (gid < 256)   g_hcoarse[gid] = 0;
}

// =================== K4: bitonic sort (warp-sync inner stages) ============
__global__ void __launch_bounds__(1024) sort_kernel() {
    extern __shared__ ull sk[];
    int tid = threadIdx.x;
    int M = g_candcount; if (M > CAP) M = CAP;
    int P = 2048;
    while (P < M) P <<= 1;
    int epw = P >> 10;                     // elements per thread (strided)
    for (int e = 0; e < epw; e++) {
        int i = tid + (e << 10);
        sk[i] = (i < M) ? g_cand[i] : 0ULL;
    }
    __syncthreads();
    if (tid == 0) g_candcount = 0;         // reset after M consumed
    for (int k = 2; k <= P; k <<= 1) {
        for (int j = k >> 1; j > 0; j >>= 1) {
            for (int e = 0; e < epw; e++) {
                int i = tid + (e << 10);
                int l = i ^ j;
                if (l > i) {
                    bool desc = ((i & k) == 0);
                    ull a = sk[i], b = sk[l];
                    if (desc ? (a < b) : (a > b)) { sk[i] = b; sk[l] = a; }
                }
            }
            // partners within a warp when j<32 (strided element ownership)
            if (j >= 32) __syncthreads();
            else         __syncwarp(0xFFFFFFFFu);
        }
    }
    __syncthreads();
    for (int i = tid; i < TOPK; i += 1024) {
        unsigned n = ~(unsigned)(sk[i] & 0xFFFFFFFFULL);
        g_topboxes[i] = g_boxper[n];
    }
}

// =================== K5: NMS suppression bitmask ==========================
__global__ void __launch_bounds__(256) nms_mask_kernel() {
    __shared__ float4 sb[64];
    int cb = blockIdx.x;
    int t  = threadIdx.x;
    int col0 = cb * 64;
    if (t < 64 && col0 + t < TOPK) sb[t] = g_topboxes[col0 + t];
    __syncthreads();
    int row = blockIdx.y * 256 + t;
    if (row >= TOPK) return;
    float4 a = g_topboxes[row];
    float aarea = (a.z - a.x) * (a.w - a.y);
    ull bits = 0;
    int nj = min(64, TOPK - col0);
    for (int j = 0; j < nj; j++) {
        float4 b = sb[j];
        float lx = fmaxf(a.x, b.x), ly = fmaxf(a.y, b.y);
        float rx = fminf(a.z, b.z), ry = fminf(a.w, b.w);
        float iw = fmaxf(rx - lx, 0.f), ih = fmaxf(ry - ly, 0.f);
        float inter = iw * ih;
        float barea = (b.z - b.x) * (b.w - b.y);
        float iou = __fdividef(inter, aarea + barea - inter);
        if (iou > NMS_THR) bits |= (1ULL << j);   // NaN compares false
    }
    g_mask[row * CBLK + cb] = bits;
}

// =================== K6: greedy scan + final write ========================
__global__ void __launch_bounds__(256) nms_final_kernel(float* __restrict__ out) {
    __shared__ ull skeep[CBLK];
    int t = threadIdx.x;
    if (t < 32) {
        ull rem = 0;        // lane t: OR of suppression for column block t
        ull cur_sup = 0;    // replicated: suppression word of current 64-row block
        ull kw = 0;         // keep bits of current block (replicated)
        ull bit = 1;
        const int D = 8;
        ull buf[D];
        #pragma unroll
        for (int k = 0; k < D; k++) buf[k] = g_mask[k * CBLK + t];
        ull m0 = __shfl_sync(0xFFFFFFFFu, buf[0], 0);
        ull m1 = __shfl_sync(0xFFFFFFFFu, buf[1], 0);
        for (int i = 0; i < TOPK; i++) {
            ull cur = buf[i & (D - 1)];
            ull m2 = 0;
            if (i + 2 < TOPK)
                m2 = __shfl_sync(0xFFFFFFFFu, buf[(i + 2) & (D - 1)], (i + 2) >> 6);
            if (i + D < TOPK) buf[i & (D - 1)] = g_mask[(i + D) * CBLK + t];

            bool keep = (cur_sup & bit) == 0ULL;
            if (keep) { cur_sup |= m0; kw |= bit; }
            rem |= keep ? cur : 0ULL;

            if ((i & 63) == 63) {
                if (t == 0) skeep[i >> 6] = kw;
                kw = 0; bit = 1;
                cur_sup = __shfl_sync(0xFFFFFFFFu, rem, (i + 1) >> 6);
            } else {
                bit <<= 1;
            }
            m0 = m1; m1 = m2;
        }
        if (t == 0) skeep[(TOPK - 1) >> 6] = kw;
    }
    __syncthreads();
    const float* tb = (const float*)g_topboxes;
    for (int idx = t; idx < TOPK * 4; idx += 256) {
        int r = idx >> 2;
        float k = ((skeep[r >> 6] >> (r & 63)) & 1ULL) ? 1.0f : 0.0f;
        out[idx] = tb[idx] * k;
    }
}

// ---------------- launcher: 6 graph nodes ----------------
extern "C" void kernel_launch(void* const* d_in, const int* in_sizes, int n_in,
                              void* d_out, int out_size)
{
    const float4* prop = (const float4*)d_in[0];
    const float4* btp  = (const float4*)d_in[1];
    const float*  cls  = (const float*)d_in[2];
    const float4* gt   = (const float4*)d_in[3];
    const int*    ih   = (const int*)d_in[4];
    const int*    iw   = (const int*)d_in[5];
    float*        out  = (float*)d_out;

    int N = in_sizes[0] / 4;
    int C = in_sizes[2] / N;
    int G = in_sizes[3] / 4;

    static int smem_set = 0;
    if (!smem_set) {
        cudaFuncSetAttribute(sort_kernel,
                             cudaFuncAttributeMaxDynamicSharedMemorySize,
                             CAP * (int)sizeof(ull));
        smem_set = 1;
    }

    int smem_main = BM * 21 * (int)sizeof(float);
    main_kernel<<<(N + BM - 1) / BM, BM, smem_main>>>(
        prop, btp, cls, gt, ih, iw, (float4*)out, N, C, G);

    findbin_kernel<<<1, 256>>>();
    compact_kernel<<<(N + 255) / 256, 256>>>(N);
    sort_kernel<<<1, 1024, CAP * sizeof(ull)>>>();

    dim3 grid((TOPK + 63) / 64, (TOPK + 255) / 256);
    nms_mask_kernel<<<grid, 256>>>();
    nms_final_kernel<<<1, 256>>>(out);
}

// round 7
// speedup vs baseline: 1.0372x; 1.0372x over previous
#include <cuda_runtime.h>
#include <cstdint>

#define TOPK      2000
#define NMS_THR   0.5f
#define MAXN      200000
#define MAXG      128
#define HBINS     65536
#define CAP       8192
#define CBLK      32          // ceil(TOPK/64)
#define BM        256         // proposals per block in main kernel

typedef unsigned long long ull;

// ---------------- scratch (no allocation allowed) ----------------
__device__ float               g_score[MAXN];
__device__ float4              g_boxper[MAXN];
__device__ __align__(16) int   g_hist[HBINS];    // zero at load; re-zeroed in compact
__device__ int                 g_candcount;      // zero at load; reset in sort
__device__ int                 g_binB;
__device__ ull                 g_cand[CAP];
__device__ float4              g_topboxes[TOPK];
__device__ ull                 g_mask[TOPK * CBLK];

// =================== K1: fused per-proposal ==========
__global__ void __launch_bounds__(BM) main_kernel(
        const float4* __restrict__ prop,
        const float4* __restrict__ btp,   // (N*C) float4
        const float*  __restrict__ cls,
        const float4* __restrict__ gt,
        const int* __restrict__ ihp,
        const int* __restrict__ iwp,
        float4* __restrict__ out,         // full output, rows (TOPK+n)
        int N, int C, int G)
{
    __shared__ float4 sgtb[MAXG];
    __shared__ float  sga[MAXG];
    extern __shared__ float scls[];       // BM*21 floats (stride 21 -> conflict-free)

    int tid = threadIdx.x;
    int n0  = blockIdx.x * BM;

    int vi = ihp[0];
    float H = (vi > 0 && vi < 1000000) ? (float)vi : __int_as_float(vi);
    vi = iwp[0];
    float W = (vi > 0 && vi < 1000000) ? (float)vi : __int_as_float(vi);

    for (int i = tid; i < G && i < MAXG; i += BM) {
        float4 g = gt[i];
        sgtb[i] = g;
        sga[i]  = (g.z - g.x) * (g.w - g.y);
    }
    // stage cls rows (coalesced global reads)
    {
        int rows = min(BM, N - n0);
        if (rows > 0) {
            const float* cbase = cls + (size_t)n0 * C;
            if (C == 21) {
                int total = rows * 21;
                for (int idx = tid; idx < total; idx += BM) {
                    int r = idx / 21;
                    scls[r * 21 + (idx - r * 21)] = cbase[idx];
                }
            } else {
                int total = rows * C;
                for (int idx = tid; idx < total; idx += BM) {
                    int r = idx / C;
                    scls[r * 21 + (idx - r * C)] = cbase[idx];
                }
            }
        }
    }
    __syncthreads();

    int n = n0 + tid;
    if (n >= N) return;

    float4 p = prop[n];
    float pw = p.z - p.x, ph = p.w - p.y;
    float pcx = p.x + 0.5f * pw, pcy = p.y + 0.5f * ph;
    float parea = pw * ph;

    // softmax score + fg argmax (from shared)
    const float* cr = scls + tid * 21;
    float m = cr[0], bl = -1e30f; int bc = 1;
    #pragma unroll
    for (int c = 1; c < 21; c++) {
        float v = cr[c];
        m = fmaxf(m, v);
        if (v > bl) { bl = v; bc = c; }
    }
    float Z = 0.f;
    #pragma unroll
    for (int c = 0; c < 21; c++) Z += __expf(cr[c] - m);
    float score = __fdividef(__expf(bl - m), Z);

    // decode selected class box, clamp
    float4 t = btp[(size_t)n * C + bc];
    float dcx = t.x * pw + pcx;
    float dcy = t.y * ph + pcy;
    float dw  = __expf(t.z) * pw;
    float dh  = __expf(t.w) * ph;
    float4 box;
    box.x = fminf(fmaxf(dcx - 0.5f * dw, 0.f), W);
    box.y = fminf(fmaxf(dcy - 0.5f * dh, 0.f), H);
    box.z = fminf(fmaxf(dcx + 0.5f * dw, 0.f), W);
    box.w = fminf(fmaxf(dcy + 0.5f * dh, 0.f), H);

    g_boxper[n] = box;
    g_score[n]  = score;
    atomicAdd(&g_hist[__float_as_uint(score) >> 16], 1);

    // best-IoU gt match: argmax via cross-multiply, 4 independent streams
    int bg;
    #define IOU_STEP(gg, nn, dd, ii)                                   \
        {   float4 gb = sgtb[(gg)];                                    \
            float lx = fmaxf(gb.x, p.x);                               \
            float ly = fmaxf(gb.y, p.y);                               \
            float rx = fminf(gb.z, p.z);                               \
            float ry = fminf(gb.w, p.w);                               \
            float iw = fmaxf(rx - lx, 0.f), ihh = fmaxf(ry - ly, 0.f); \
            float inter = iw * ihh;                                    \
            float den = sga[(gg)] + parea - inter;                     \
            if (inter * (dd) > (nn) * den) { (nn) = inter; (dd) = den; (ii) = (gg); } }
    if (G == 128) {
        float fn0 = -1.f, fd0 = 1.f, fn1 = -1.f, fd1 = 1.f;
        float fn2 = -1.f, fd2 = 1.f, fn3 = -1.f, fd3 = 1.f;
        int   i0 = 0, i1 = 32, i2 = 64, i3 = 96;
        #pragma unroll 4
        for (int g = 0; g < 32; g++) {
            IOU_STEP(g,      fn0, fd0, i0);
            IOU_STEP(g + 32, fn1, fd1, i1);
            IOU_STEP(g + 64, fn2, fd2, i2);
            IOU_STEP(g + 96, fn3, fd3, i3);
        }
        // ordered merge: prefer earlier stream on ties (strict >)
        if (fn1 * fd0 > fn0 * fd1) { fn0 = fn1; fd0 = fd1; i0 = i1; }
        if (fn2 * fd0 > fn0 * fd2) { fn0 = fn2; fd0 = fd2; i0 = i2; }
        if (fn3 * fd0 > fn0 * fd3) { fn0 = fn3; fd0 = fd3; i0 = i3; }
        bg = i0;
    } else {
        float fn0 = -1.f, fd0 = 1.f; int i0 = 0;
        for (int g = 0; g < G; g++) IOU_STEP(g, fn0, fd0, i0);
        bg = i0;
    }
    #undef IOU_STEP

    float4 gb = sgtb[bg];
    float gw = gb.z - gb.x, gh = gb.w - gb.y;
    float gcx = gb.x + 0.5f * gw, gcy = gb.y + 0.5f * gh;
    float4 rt;
    rt.x = __fdividef(gcx - pcx, pw);
    rt.y = __fdividef(gcy - pcy, ph);
    rt.z = __logf(__fdividef(gw, pw));
    rt.w = __logf(__fdividef(gh, ph));
    out[TOPK + n] = rt;
}

// =================== K2: findbin, 1024 threads, warp-parallel fine walk ====
__global__ void __launch_bounds__(1024) findbin_kernel() {
    __shared__ int csum[1024];
    __shared__ int wsum[32];
    __shared__ int s_chunk, s_excl;
    int tid = threadIdx.x;
    int w = tid >> 5, lane = tid & 31;

    // chunk sums: warp w handles chunks w, w+32, ... (chunk 0 = top scores)
    for (int c = w; c < 1024; c += 32) {
        int base = HBINS - (c + 1) * 64;
        int s = g_hist[base + lane] + g_hist[base + 32 + lane];
        s = __reduce_add_sync(0xFFFFFFFFu, s);
        if (lane == 0) csum[c] = s;
    }
    __syncthreads();

    // block-wide inclusive scan over 1024 chunk sums
    int v = csum[tid];
    int x = v;
    #pragma unroll
    for (int o = 1; o < 32; o <<= 1) {
        int y = __shfl_up_sync(0xFFFFFFFFu, x, o);
        if (lane >= o) x += y;
    }
    if (lane == 31) wsum[w] = x;
    __syncthreads();
    if (w == 0) {
        int s = wsum[lane];
        #pragma unroll
        for (int o = 1; o < 32; o <<= 1) {
            int y = __shfl_up_sync(0xFFFFFFFFu, s, o);
            if (lane >= o) s += y;
        }
        wsum[lane] = s;
    }
    __syncthreads();
    int incl = x + ((w > 0) ? wsum[w - 1] : 0);
    int excl = incl - v;
    if (excl < TOPK && incl >= TOPK) { s_chunk = tid; s_excl = excl; }
    __syncthreads();

    // warp 0: fine scan inside the boundary chunk (descending bins)
    if (w == 0) {
        int chunk = s_chunk, be = s_excl;
        int base = HBINS - (chunk + 1) * 64;
        int x0 = g_hist[base + 63 - lane];   // desc pos = lane
        int x1 = g_hist[base + 31 - lane];   // desc pos = lane+32
        int s0 = x0;
        #pragma unroll
        for (int o = 1; o < 32; o <<= 1) {
            int y = __shfl_up_sync(0xFFFFFFFFu, s0, o);
            if (lane >= o) s0 += y;
        }
        int t0 = __shfl_sync(0xFFFFFFFFu, s0, 31);
        int s1 = x1;
        #pragma unroll
        for (int o = 1; o < 32; o <<= 1) {
            int y = __shfl_up_sync(0xFFFFFFFFu, s1, o);
            if (lane >= o) s1 += y;
        }
        int incl0 = be + s0, excl0 = incl0 - x0;
        if (excl0 < TOPK && incl0 >= TOPK) g_binB = base + 63 - lane;
        int incl1 = be + t0 + s1, excl1 = incl1 - x1;
        if (excl1 < TOPK && incl1 >= TOPK) g_binB = base + 31 - lane;
    }
}

// =================== K3: compact + hist re-zero ============
__global__ void __launch_bounds__(256) compact_kernel(int N) {
    int gid = blockIdx.x * 256 + threadIdx.x;
    if (gid < N) {
        unsigned bits = __float_as_uint(g_score[gid]);
        if ((int)(bits >> 16) >= g_binB) {
            int pos = atomicAdd(&g_candcount, 1);
            if (pos < CAP)
                g_cand[pos] = ((ull)bits << 32) | (unsigned)(~gid);
        }
    }
    if (gid < HBINS) g_hist[gid] = 0;      // parallel re-zero for next replay
}

// bitonic shfl pass on a register-resident element (j <= 16, intra-warp)
__device__ __forceinline__ void shfl_pass(ull& v, int i, int j, int k) {
    ull wv = __shfl_xor_sync(0xFFFFFFFFu, v, j);
    bool desc  = ((i & k) == 0);
    bool lower = ((i & j) == 0);
    bool takeMax = (desc == lower);
    bool gt = v > wv;
    v = (takeMax == gt) ? v : wv;
}

__device__ __forceinline__ void safe_gather(int pos, ull key) {
    unsigned n = ~(unsigned)(key & 0xFFFFFFFFULL);
    if (n >= MAXN) n = 0;                  // defensive: never OOB
    g_topboxes[pos] = g_boxper[n];
}

// =================== K4: bitonic sort (regs+shfl inner passes) ============
__global__ void __launch_bounds__(1024) sort_kernel() {
    extern __shared__ ull sk[];
    int t = threadIdx.x;
    int M = g_candcount; if (M > CAP) M = CAP;
    __syncthreads();                       // ALL threads read candcount first
    if (t == 0) g_candcount = 0;           // then reset for next replay
    int P = 2048;
    while (P < M) P <<= 1;

    if (P == 2048) {
        // fast path: thread t owns i0=t, i1=t+1024 in registers
        const int i0 = t, i1 = t + 1024;
        ull v0 = (i0 < M) ? g_cand[i0] : 0ULL;
        ull v1 = (i1 < M) ? g_cand[i1] : 0ULL;
        // stages k=2..32: fully intra-warp
        #pragma unroll
        for (int k = 2; k <= 32; k <<= 1)
            #pragma unroll
            for (int j = k >> 1; j > 0; j >>= 1) {
                shfl_pass(v0, i0, j, k);
                shfl_pass(v1, i1, j, k);
            }
        // stages k=64..2048: j>=32 via smem, j<=16 via shfl
        for (int k = 64; k <= 2048; k <<= 1) {
            sk[i0] = v0; sk[i1] = v1;
            __syncthreads();
            for (int j = k >> 1; j >= 32; j >>= 1) {
                #pragma unroll
                for (int e = 0; e < 2; e++) {
                    int i = t + (e << 10);
                    int l = i ^ j;
                    if (l > i) {
                        bool desc = ((i & k) == 0);
                        ull a = sk[i], b = sk[l];
                        if (desc ? (a < b) : (a > b)) { sk[i] = b; sk[l] = a; }
                    }
                }
                __syncthreads();
            }
            v0 = sk[i0]; v1 = sk[i1];
            #pragma unroll
            for (int j = 16; j > 0; j >>= 1) {
                shfl_pass(v0, i0, j, k);
                shfl_pass(v1, i1, j, k);
            }
        }
        // gather: position i holds i-th largest
        if (i0 < TOPK) safe_gather(i0, v0);
        if (i1 < TOPK) safe_gather(i1, v1);
    } else {
        // generic fallback (rare: huge tie bin)
        int epw = P >> 10;
        for (int e = 0; e < epw; e++) {
            int i = t + (e << 10);
            sk[i] = (i < M) ? g_cand[i] : 0ULL;
        }
        __syncthreads();
        for (int k = 2; k <= P; k <<= 1)
            for (int j = k >> 1; j > 0; j >>= 1) {
                for (int e = 0; e < epw; e++) {
                    int i = t + (e << 10);
                    int l = i ^ j;
                    if (l > i) {
                        bool desc = ((i & k) == 0);
                        ull a = sk[i], b = sk[l];
                        if (desc ? (a < b) : (a > b)) { sk[i] = b; sk[l] = a; }
                    }
                }
                __syncthreads();
            }
        for (int i = t; i < TOPK; i += 1024) safe_gather(i, sk[i]);
    }
}

// =================== K5: NMS suppression bitmask ==========================
__global__ void __launch_bounds__(256) nms_mask_kernel() {
    __shared__ float4 sb[64];
    int cb = blockIdx.x;
    int t  = threadIdx.x;
    int col0 = cb * 64;
    if (t < 64 && col0 + t < TOPK) sb[t] = g_topboxes[col0 + t];
    __syncthreads();
    int row = blockIdx.y * 256 + t;
    if (row >= TOPK) return;
    float4 a = g_topboxes[row];
    float aarea = (a.z - a.x) * (a.w - a.y);
    ull bits = 0;
    int nj = min(64, TOPK - col0);
    for (int j = 0; j < nj; j++) {
        float4 b = sb[j];
        float lx = fmaxf(a.x, b.x), ly = fmaxf(a.y, b.y);
        float rx = fminf(a.z, b.z), ry = fminf(a.w, b.w);
        float iw = fmaxf(rx - lx, 0.f), ih = fmaxf(ry - ly, 0.f);
        float inter = iw * ih;
        float barea = (b.z - b.x) * (b.w - b.y);
        float iou = __fdividef(inter, aarea + barea - inter);
        if (iou > NMS_THR) bits |= (1ULL << j);   // NaN compares false
    }
    g_mask[row * CBLK + cb] = bits;
}

// =================== K6: greedy scan + final write ========================
__global__ void __launch_bounds__(256) nms_final_kernel(float* __restrict__ out) {
    __shared__ ull skeep[CBLK];
    int t = threadIdx.x;
    if (t < 32) {
        ull rem = 0;        // lane t: OR of suppression for column block t
        ull cur_sup = 0;    // replicated: suppression word of current 64-row block
        ull kw = 0;         // keep bits of current block (replicated)
        ull bit = 1;
        const int D = 16;
        ull buf[D];
        #pragma unroll
        for (int k = 0; k < D; k++) buf[k] = g_mask[k * CBLK + t];
        ull m0 = __shfl_sync(0xFFFFFFFFu, buf[0], 0);
        ull m1 = __shfl_sync(0xFFFFFFFFu, buf[1], 0);
        ull m2 = __shfl_sync(0xFFFFFFFFu, buf[2], 0);
        ull m3 = __shfl_sync(0xFFFFFFFFu, buf[3], 0);
        for (int i = 0; i < TOPK; i++) {
            ull cur = buf[i & (D - 1)];
            ull mn = 0;
            if (i + 4 < TOPK)
                mn = __shfl_sync(0xFFFFFFFFu, buf[(i + 4) & (D - 1)], (i + 4) >> 6);
            if (i + D < TOPK) buf[i & (D - 1)] = g_mask[(i + D) * CBLK + t];

            bool keep = (cur_sup & bit) == 0ULL;
            if (keep) { cur_sup |= m0; kw |= bit; }
            rem |= keep ? cur : 0ULL;

            if ((i & 63) == 63) {
                if (t == 0) skeep[i >> 6] = kw;
                kw = 0; bit = 1;
                cur_sup = __shfl_sync(0xFFFFFFFFu, rem, (i + 1) >> 6);
            } else {
                bit <<= 1;
            }
            m0 = m1; m1 = m2; m2 = m3; m3 = mn;
        }
        if (t == 0) skeep[(TOPK - 1) >> 6] = kw;
    }
    __syncthreads();
    const float* tb = (const float*)g_topboxes;
    for (int idx = t; idx < TOPK * 4; idx += 256) {
        int r = idx >> 2;
        float k = ((skeep[r >> 6] >> (r & 63)) & 1ULL) ? 1.0f : 0.0f;
        out[idx] = tb[idx] * k;
    }
}

// ---------------- launcher: 6 graph nodes ----------------
extern "C" void kernel_launch(void* const* d_in, const int* in_sizes, int n_in,
                              void* d_out, int out_size)
{
    const float4* prop = (const float4*)d_in[0];
    const float4* btp  = (const float4*)d_in[1];
    const float*  cls  = (const float*)d_in[2];
    const float4* gt   = (const float4*)d_in[3];
    const int*    ih   = (const int*)d_in[4];
    const int*    iw   = (const int*)d_in[5];
    float*        out  = (float*)d_out;

    int N = in_sizes[0] / 4;
    int C = in_sizes[2] / N;
    int G = in_sizes[3] / 4;

    static int smem_set = 0;
    if (!smem_set) {
        cudaFuncSetAttribute(sort_kernel,
                             cudaFuncAttributeMaxDynamicSharedMemorySize,
                             CAP * (int)sizeof(ull));
        smem_set = 1;
    }

    int smem_main = BM * 21 * (int)sizeof(float);
    main_kernel<<<(N + BM - 1) / BM, BM, smem_main>>>(
        prop, btp, cls, gt, ih, iw, (float4*)out, N, C, G);

    findbin_kernel<<<1, 1024>>>();
    compact_kernel<<<(N + 255) / 256, 256>>>(N);
    sort_kernel<<<1, 1024, CAP * sizeof(ull)>>>();

    dim3 grid((TOPK + 63) / 64, (TOPK + 255) / 256);
    nms_mask_kernel<<<grid, 256>>>();
    nms_final_kernel<<<1, 256>>>(out);
}